// round 14
// baseline (speedup 1.0000x reference)
#include <cuda_runtime.h>
#include <math.h>

// Problem shape (fixed): x [T=4, B=32, C=256, H=32, W=32]
#define Tn 4
#define Bn 32
#define Cn 256
#define Pn 1024
#define NSL 1024            // slices = B * 32 pixel-groups (32 pixels each, all channels)
#define NBLK 148            // phase-1 CTAs = one per SM (wave 1)
#define NGRID (NBLK + Bn)   // + 32 wave-2 finale CTAs

// Per-pixel sums: [sel][b][p], sel 0 = csum, 1 = ssq. 256 KB, L2-resident.
__device__ float g_comb[2 * Bn * Pn];
// Per-batch slice-completion counters (reset by the finale block that consumes them).
__device__ int g_done[Bn];

// ---------------------------------------------------------------------------
// Single launch, two block roles.
// Blocks 0..147 (phase 1): R13 persistent reduce, UNCHANGED loop.
//   Slice = (b, pg): 32 pixels x 256 channels x 4 t. warp w: channels
//   [8w,8w+8); lane l: f4=l&7, cpair=l>>3. 8 x LDG.128/thread/slice, next
//   slice prefetched. Transposed scalar combine (pad-33, conflict-free),
//   parity double-buffer -> one barrier per slice.
//   Post-loop: release fence + atomicAdd(g_done[b]) per owned slice.
// Blocks 148..179 (finale, wave 2): spin until batch b's 32 slices published,
//   then box filter + cosine collapse + softmax for batch b. Runs on SMs as
//   they free (CLC wave transition ~1.2us), 32 finales in parallel.
// ---------------------------------------------------------------------------
__global__ void __launch_bounds__(1024, 1) fused_kernel(const float* __restrict__ xf,
                                                        const int* __restrict__ mask,
                                                        float* __restrict__ out) {
    const int tid = threadIdx.x;

    if (blockIdx.x >= NBLK) {
        // ================= finale block: batch b =================
        const int b = blockIdx.x - NBLK;

        if (tid == 0) {
            while (*(volatile int*)&g_done[b] < Bn) __nanosleep(64);
            atomicExch(&g_done[b], 0);        // reset for next graph replay
        }
        __syncthreads();
        __threadfence();                      // acquire: see publishers' g_comb

        const int h    = tid >> 5;
        const int w2   = tid & 31;
        const int lane = tid & 31;
        const int wid  = tid >> 5;

        // plain loads (coherent path) — NOT __ldg/ld.nc
        const float cs = g_comb[(size_t)b * Pn + tid];
        const float sq = g_comb[(size_t)(Bn + b) * Pn + tid];
        const int mraw = __ldg(&mask[(size_t)b * Pn + tid]);

        __shared__ float s_cs[34 * 34];
        __shared__ float red[32];
        __shared__ float bc[2];

        for (int i = tid; i < 34 * 34; i += 1024) s_cs[i] = 0.f;
        __syncthreads();
        s_cs[(h + 1) * 34 + (w2 + 1)] = cs;
        __syncthreads();

        float box = 0.f;
#pragma unroll
        for (int dh = 0; dh < 3; ++dh)
#pragma unroll
            for (int dw = 0; dw < 3; ++dw)
                box += s_cs[(h + dh) * 34 + (w2 + dw)];

        const float lm  = box * (1.f / 9.f);
        const float nx  = sqrtf(sq);
        const float ny  = 16.f * fabsf(lm);       // sqrt(C)=16
        const float sim = (lm * cs) / (fmaxf(nx, 1e-6f) * fmaxf(ny, 1e-6f));
        const float score = mraw ? -INFINITY : -sim;

        float m = score;
#pragma unroll
        for (int o = 16; o; o >>= 1) m = fmaxf(m, __shfl_xor_sync(0xFFFFFFFFu, m, o));
        if (lane == 0) red[wid] = m;
        __syncthreads();
        if (wid == 0) {
            float v = red[lane];
#pragma unroll
            for (int o = 16; o; o >>= 1) v = fmaxf(v, __shfl_xor_sync(0xFFFFFFFFu, v, o));
            if (lane == 0) bc[0] = v;
        }
        __syncthreads();
        const float gmax = bc[0];

        const float e = __expf(score - gmax);
        float s = e;
#pragma unroll
        for (int o = 16; o; o >>= 1) s += __shfl_xor_sync(0xFFFFFFFFu, s, o);
        if (lane == 0) red[wid] = s;
        __syncthreads();
        if (wid == 0) {
            float v = red[lane];
#pragma unroll
            for (int o = 16; o; o >>= 1) v += __shfl_xor_sync(0xFFFFFFFFu, v, o);
            if (lane == 0) bc[1] = v;
        }
        __syncthreads();

        out[(size_t)b * Pn + tid] = e * __frcp_rn(bc[1]);
        return;
    }

    // ================= phase-1 block: persistent reduce (R13) =================
    const float4* __restrict__ X = (const float4*)xf;
    const int w     = tid >> 5;            // 0..31
    const int l     = tid & 31;
    const int f4    = l & 7;
    const int cbase = w * 8 + (l >> 3) * 2;

    // [parity][warp][33] scalars; pad 33 makes column reads conflict-free.
    __shared__ float scs[2][32][33];
    __shared__ float ssq[2][32][33];

    const size_t tstr = (size_t)Bn * Cn * 256;   // t-plane stride in float4

    int sl  = blockIdx.x;
    int par = 0;
    float4 r[8];
    {
        const int b = sl >> 5, pg = sl & 31;
        const size_t base = ((size_t)b * Cn + cbase) * 256 + pg * 8 + f4;
#pragma unroll
        for (int t = 0; t < 4; ++t) {
            r[t]     = __ldg(X + base + (size_t)t * tstr);
            r[4 + t] = __ldg(X + base + 256 + (size_t)t * tstr);
        }
    }

    for (;;) {
        float4 m0, m1;
        m0.x = (r[0].x + r[1].x + r[2].x + r[3].x) * 0.25f;
        m0.y = (r[0].y + r[1].y + r[2].y + r[3].y) * 0.25f;
        m0.z = (r[0].z + r[1].z + r[2].z + r[3].z) * 0.25f;
        m0.w = (r[0].w + r[1].w + r[2].w + r[3].w) * 0.25f;
        m1.x = (r[4].x + r[5].x + r[6].x + r[7].x) * 0.25f;
        m1.y = (r[4].y + r[5].y + r[6].y + r[7].y) * 0.25f;
        m1.z = (r[4].z + r[5].z + r[6].z + r[7].z) * 0.25f;
        m1.w = (r[4].w + r[5].w + r[6].w + r[7].w) * 0.25f;

        float4 cs4, sq4;
        cs4.x = m0.x + m1.x;  cs4.y = m0.y + m1.y;
        cs4.z = m0.z + m1.z;  cs4.w = m0.w + m1.w;
        sq4.x = fmaf(m0.x, m0.x, m1.x * m1.x);
        sq4.y = fmaf(m0.y, m0.y, m1.y * m1.y);
        sq4.z = fmaf(m0.z, m0.z, m1.z * m1.z);
        sq4.w = fmaf(m0.w, m0.w, m1.w * m1.w);

        const int cur  = sl;
        const int nxt  = sl + NBLK;
        const bool more = (nxt < NSL);

        if (more) {   // issue next slice's loads NOW; they fly across the reduction
            const int b = nxt >> 5, pg = nxt & 31;
            const size_t base = ((size_t)b * Cn + cbase) * 256 + pg * 8 + f4;
#pragma unroll
            for (int t = 0; t < 4; ++t) {
                r[t]     = __ldg(X + base + (size_t)t * tstr);
                r[4 + t] = __ldg(X + base + 256 + (size_t)t * tstr);
            }
        }

        // reduce over the 4 cpair-threads sharing this f4 within the warp
#pragma unroll
        for (int off = 8; off <= 16; off <<= 1) {
            cs4.x += __shfl_xor_sync(0xFFFFFFFFu, cs4.x, off);
            cs4.y += __shfl_xor_sync(0xFFFFFFFFu, cs4.y, off);
            cs4.z += __shfl_xor_sync(0xFFFFFFFFu, cs4.z, off);
            cs4.w += __shfl_xor_sync(0xFFFFFFFFu, cs4.w, off);
            sq4.x += __shfl_xor_sync(0xFFFFFFFFu, sq4.x, off);
            sq4.y += __shfl_xor_sync(0xFFFFFFFFu, sq4.y, off);
            sq4.z += __shfl_xor_sync(0xFFFFFFFFu, sq4.z, off);
            sq4.w += __shfl_xor_sync(0xFFFFFFFFu, sq4.w, off);
        }
        // lanes 0..7 hold this warp's partials for ff=l: store as scalars j=4l..4l+3
        if (l < 8) {
            scs[par][w][l * 4 + 0] = cs4.x;
            scs[par][w][l * 4 + 1] = cs4.y;
            scs[par][w][l * 4 + 2] = cs4.z;
            scs[par][w][l * 4 + 3] = cs4.w;
            ssq[par][w][l * 4 + 0] = sq4.x;
            ssq[par][w][l * 4 + 1] = sq4.y;
            ssq[par][w][l * 4 + 2] = sq4.z;
            ssq[par][w][l * 4 + 3] = sq4.w;
        }
        __syncthreads();      // the ONLY barrier per slice (parity double-buffer)

        // transposed combine: warp w reduces scalar j=w across all 32 warps.
        // column read scs[par][l][w]: bank = (l + w) % 32 -> conflict-free
        {
            float vc = scs[par][l][w];
            float vq = ssq[par][l][w];
#pragma unroll
            for (int off = 16; off; off >>= 1) {
                vc += __shfl_xor_sync(0xFFFFFFFFu, vc, off);
                vq += __shfl_xor_sync(0xFFFFFFFFu, vq, off);
            }
            if (l == 0) {
                const int b = cur >> 5, pg = cur & 31;
                const int o = b * 1024 + pg * 32 + w;   // scalar j=w of this slice
                g_comb[o] = vc;
                g_comb[Bn * Pn + o] = vq;
            }
        }

        if (!more) break;
        par ^= 1;
        sl = nxt;
    }

    // ---- publish: writers (lane 0 of each warp) release, then count slices ----
    if (l == 0) __threadfence();
    __syncthreads();
    if (tid == 0) {
        for (int s = blockIdx.x; s < NSL; s += NBLK)
            atomicAdd(&g_done[s >> 5], 1);
    }
}

// ---------------------------------------------------------------------------
extern "C" void kernel_launch(void* const* d_in, const int* in_sizes, int n_in,
                              void* d_out, int out_size) {
    const float* x = (const float*)d_in[0];
    const int* mask = (const int*)d_in[1];
    float* out = (float*)d_out;

    fused_kernel<<<NGRID, 1024>>>(x, mask, out);
}

// round 15
// speedup vs baseline: 1.1415x; 1.1415x over previous
#include <cuda_runtime.h>
#include <math.h>

// Problem shape (fixed): x [T=4, B=32, C=256, H=32, W=32]
#define Tn 4
#define Bn 32
#define Cn 256
#define Pn 1024
#define NSL 1024            // slices = B * 32 pixel-groups (32 pixels each, all channels)
#define NBLK 148            // persistent grid = one CTA per SM

// Per-pixel sums: [sel][b][p], sel 0 = csum, 1 = ssq. 256 KB, L2-resident.
__device__ float g_comb[2 * Bn * Pn];

// ---------------------------------------------------------------------------
// Persistent reduce (R13, unchanged). Slice = (b, pg): 32 pixels x 256
// channels x 4 t. warp w: channels [8w,8w+8); lane l: f4=l&7, cpair=l>>3.
// 8 x LDG.128 per thread/slice; next slice prefetched across the reduction.
// Transposed scalar combine (pad-33, conflict-free), parity double-buffer ->
// one barrier per slice.
// ---------------------------------------------------------------------------
__global__ void __launch_bounds__(1024, 1) reduce_kernel(const float* __restrict__ xf) {
    const float4* __restrict__ X = (const float4*)xf;
    const int tid   = threadIdx.x;
    const int w     = tid >> 5;            // 0..31
    const int l     = tid & 31;
    const int f4    = l & 7;
    const int cbase = w * 8 + (l >> 3) * 2;

    __shared__ float scs[2][32][33];
    __shared__ float ssq[2][32][33];

    const size_t tstr = (size_t)Bn * Cn * 256;   // t-plane stride in float4

    int sl  = blockIdx.x;
    int par = 0;
    float4 r[8];
    {
        const int b = sl >> 5, pg = sl & 31;
        const size_t base = ((size_t)b * Cn + cbase) * 256 + pg * 8 + f4;
#pragma unroll
        for (int t = 0; t < 4; ++t) {
            r[t]     = __ldg(X + base + (size_t)t * tstr);
            r[4 + t] = __ldg(X + base + 256 + (size_t)t * tstr);
        }
    }

    for (;;) {
        float4 m0, m1;
        m0.x = (r[0].x + r[1].x + r[2].x + r[3].x) * 0.25f;
        m0.y = (r[0].y + r[1].y + r[2].y + r[3].y) * 0.25f;
        m0.z = (r[0].z + r[1].z + r[2].z + r[3].z) * 0.25f;
        m0.w = (r[0].w + r[1].w + r[2].w + r[3].w) * 0.25f;
        m1.x = (r[4].x + r[5].x + r[6].x + r[7].x) * 0.25f;
        m1.y = (r[4].y + r[5].y + r[6].y + r[7].y) * 0.25f;
        m1.z = (r[4].z + r[5].z + r[6].z + r[7].z) * 0.25f;
        m1.w = (r[4].w + r[5].w + r[6].w + r[7].w) * 0.25f;

        float4 cs4, sq4;
        cs4.x = m0.x + m1.x;  cs4.y = m0.y + m1.y;
        cs4.z = m0.z + m1.z;  cs4.w = m0.w + m1.w;
        sq4.x = fmaf(m0.x, m0.x, m1.x * m1.x);
        sq4.y = fmaf(m0.y, m0.y, m1.y * m1.y);
        sq4.z = fmaf(m0.z, m0.z, m1.z * m1.z);
        sq4.w = fmaf(m0.w, m0.w, m1.w * m1.w);

        const int cur  = sl;
        const int nxt  = sl + NBLK;
        const bool more = (nxt < NSL);

        if (more) {   // issue next slice's loads NOW; they fly across the reduction
            const int b = nxt >> 5, pg = nxt & 31;
            const size_t base = ((size_t)b * Cn + cbase) * 256 + pg * 8 + f4;
#pragma unroll
            for (int t = 0; t < 4; ++t) {
                r[t]     = __ldg(X + base + (size_t)t * tstr);
                r[4 + t] = __ldg(X + base + 256 + (size_t)t * tstr);
            }
        }

        // reduce over the 4 cpair-threads sharing this f4 within the warp
#pragma unroll
        for (int off = 8; off <= 16; off <<= 1) {
            cs4.x += __shfl_xor_sync(0xFFFFFFFFu, cs4.x, off);
            cs4.y += __shfl_xor_sync(0xFFFFFFFFu, cs4.y, off);
            cs4.z += __shfl_xor_sync(0xFFFFFFFFu, cs4.z, off);
            cs4.w += __shfl_xor_sync(0xFFFFFFFFu, cs4.w, off);
            sq4.x += __shfl_xor_sync(0xFFFFFFFFu, sq4.x, off);
            sq4.y += __shfl_xor_sync(0xFFFFFFFFu, sq4.y, off);
            sq4.z += __shfl_xor_sync(0xFFFFFFFFu, sq4.z, off);
            sq4.w += __shfl_xor_sync(0xFFFFFFFFu, sq4.w, off);
        }
        if (l < 8) {
            scs[par][w][l * 4 + 0] = cs4.x;
            scs[par][w][l * 4 + 1] = cs4.y;
            scs[par][w][l * 4 + 2] = cs4.z;
            scs[par][w][l * 4 + 3] = cs4.w;
            ssq[par][w][l * 4 + 0] = sq4.x;
            ssq[par][w][l * 4 + 1] = sq4.y;
            ssq[par][w][l * 4 + 2] = sq4.z;
            ssq[par][w][l * 4 + 3] = sq4.w;
        }
        __syncthreads();      // the ONLY barrier per slice (parity double-buffer)

        // transposed combine: warp w reduces scalar j=w across all 32 warps.
        {
            float vc = scs[par][l][w];
            float vq = ssq[par][l][w];
#pragma unroll
            for (int off = 16; off; off >>= 1) {
                vc += __shfl_xor_sync(0xFFFFFFFFu, vc, off);
                vq += __shfl_xor_sync(0xFFFFFFFFu, vq, off);
            }
            if (l == 0) {
                const int b = cur >> 5, pg = cur & 31;
                const int o = b * 1024 + pg * 32 + w;
                g_comb[o] = vc;
                g_comb[Bn * Pn + o] = vq;
            }
        }

        if (!more) break;
        par ^= 1;
        sl = nxt;
    }
}

// ---------------------------------------------------------------------------
// Final v2: 256 threads per batch, 4 consecutive pixels per thread (float4).
// 8 warps ramp faster than 32; vectorized loads; shorter reduction trees.
// ---------------------------------------------------------------------------
__global__ void __launch_bounds__(256) final_kernel(const int* __restrict__ mask,
                                                    float* __restrict__ out) {
    const int b    = blockIdx.x;
    const int tid  = threadIdx.x;          // 0..255; pixels [4*tid, 4*tid+3]
    const int h    = tid >> 3;             // row 0..31
    const int w4   = tid & 7;              // quad within row
    const int lane = tid & 31;
    const int wid  = tid >> 5;             // 0..7

    // vectorized loads (g_comb in L2, mask in DRAM)
    const float4 cs4 = __ldg((const float4*)g_comb + (size_t)b * 256 + tid);
    const float4 sq4 = __ldg((const float4*)g_comb + (size_t)(Bn + b) * 256 + tid);
    const int4  mr4  = __ldg((const int4*)mask + (size_t)b * 256 + tid);

    // 3x3 zero-padded box sum over 32x32
    __shared__ float s_cs[34 * 34];
    for (int i = tid; i < 34 * 34; i += 256) s_cs[i] = 0.f;
    __syncthreads();
    {
        float* row = &s_cs[(h + 1) * 34 + (w4 * 4 + 1)];
        row[0] = cs4.x; row[1] = cs4.y; row[2] = cs4.z; row[3] = cs4.w;
    }
    __syncthreads();

    // column sums for the 6-wide window, then 4 horizontal 3-sums
    float colsum[6];
#pragma unroll
    for (int j = 0; j < 6; ++j) {
        const int c = w4 * 4 + j;          // columns [w4*4, w4*4+5] of padded grid
        colsum[j] = s_cs[h * 34 + c] + s_cs[(h + 1) * 34 + c] + s_cs[(h + 2) * 34 + c];
    }
    float box[4];
#pragma unroll
    for (int j = 0; j < 4; ++j) box[j] = colsum[j] + colsum[j + 1] + colsum[j + 2];

    // cosine collapse + mask -> 4 scores
    const float csv[4] = {cs4.x, cs4.y, cs4.z, cs4.w};
    const float sqv[4] = {sq4.x, sq4.y, sq4.z, sq4.w};
    const int   mrv[4] = {mr4.x, mr4.y, mr4.z, mr4.w};
    float score[4];
#pragma unroll
    for (int j = 0; j < 4; ++j) {
        const float lm  = box[j] * (1.f / 9.f);
        const float nx  = sqrtf(sqv[j]);
        const float ny  = 16.f * fabsf(lm);
        const float sim = (lm * csv[j]) / (fmaxf(nx, 1e-6f) * fmaxf(ny, 1e-6f));
        score[j] = mrv[j] ? -INFINITY : -sim;
    }

    // softmax over all 1024 entries: local(4) -> warp(32) -> block(8 warps)
    __shared__ float red[8];
    __shared__ float bc[2];

    float m = fmaxf(fmaxf(score[0], score[1]), fmaxf(score[2], score[3]));
#pragma unroll
    for (int o = 16; o; o >>= 1) m = fmaxf(m, __shfl_xor_sync(0xFFFFFFFFu, m, o));
    if (lane == 0) red[wid] = m;
    __syncthreads();
    if (tid < 8) {
        float v = red[tid];
#pragma unroll
        for (int o = 4; o; o >>= 1) v = fmaxf(v, __shfl_xor_sync(0xFFu, v, o));
        if (tid == 0) bc[0] = v;
    }
    __syncthreads();
    const float gmax = bc[0];

    float e[4];
    float s = 0.f;
#pragma unroll
    for (int j = 0; j < 4; ++j) { e[j] = __expf(score[j] - gmax); s += e[j]; }
#pragma unroll
    for (int o = 16; o; o >>= 1) s += __shfl_xor_sync(0xFFFFFFFFu, s, o);
    if (lane == 0) red[wid] = s;
    __syncthreads();
    if (tid < 8) {
        float v = red[tid];
#pragma unroll
        for (int o = 4; o; o >>= 1) v += __shfl_xor_sync(0xFFu, v, o);
        if (tid == 0) bc[1] = v;
    }
    __syncthreads();

    const float inv = __frcp_rn(bc[1]);
    float4 o4 = make_float4(e[0] * inv, e[1] * inv, e[2] * inv, e[3] * inv);
    ((float4*)out)[(size_t)b * 256 + tid] = o4;
}

// ---------------------------------------------------------------------------
extern "C" void kernel_launch(void* const* d_in, const int* in_sizes, int n_in,
                              void* d_out, int out_size) {
    const float* x = (const float*)d_in[0];
    const int* mask = (const int*)d_in[1];
    float* out = (float*)d_out;

    reduce_kernel<<<NBLK, 1024>>>(x);
    final_kernel<<<Bn, 256>>>(mask, out);
}